// round 7
// baseline (speedup 1.0000x reference)
#include <cuda_runtime.h>
#include <cuda_bf16.h>
#include <math.h>
#include <stdint.h>

#define NN  100000
#define NE  1600000
#define DD  128
#define NG  64
#define PHH 32
#define NTILES 782   // ceil(NN/128)
#define NSB 98       // scan blocks

// ---------------- device scratch (no allocations allowed) ----------------
__device__ int      g_deg[NN];
__device__ int      g_off[NN + 1];
__device__ int      g_fill[NN];
__device__ int      g_csr[NE];
__device__ unsigned g_agg[128];            // lookback aggregates (bit31 = valid)
__device__ int      g_gcnt[NG];
__device__ float    g_norm[NN];
__device__ float    g_pooled[NG * DD];
__device__ uint16_t g_fb[NN * DD];         // bf16 feature (f0 operand + L1 gather)
__device__ uint16_t g_xb[NN * DD];         // bf16 x1 (L2 gather)
__device__ uint16_t g_w1b[2][DD * DD];     // effective W1 per layer, [n][k], bf16
__device__ uint16_t g_w2b[2][DD * DD];     // effective W2 (x0.5) per layer, bf16

// ---------------- helpers ----------------
__device__ __forceinline__ uint32_t smem_u32(const void* p) {
    uint32_t a;
    asm("{ .reg .u64 t; cvta.to.shared.u64 t, %1; cvt.u32.u64 %0, t; }"
        : "=r"(a) : "l"(p));
    return a;
}

__device__ __forceinline__ uint32_t bf2pack(float lo, float hi) {
    uint32_t p;
    asm("cvt.rn.bf16x2.f32 %0, %1, %2;" : "=r"(p) : "f"(hi), "f"(lo));
    return p;
}

__device__ __forceinline__ uint16_t bf1(float v) {
    return (uint16_t)(bf2pack(v, 0.f) & 0xFFFFu);
}

__device__ __forceinline__ void cpa16(uint32_t dst, const void* src) {
    asm volatile("cp.async.cg.shared.global [%0], [%1], 16;"
                 :: "r"(dst), "l"(src) : "memory");
}

__device__ __forceinline__ void ldsm4(uint32_t* r, uint32_t addr) {
    asm volatile("ldmatrix.sync.aligned.m8n8.x4.shared.b16 {%0,%1,%2,%3}, [%4];"
                 : "=r"(r[0]), "=r"(r[1]), "=r"(r[2]), "=r"(r[3]) : "r"(addr));
}

__device__ __forceinline__ void mma16(float* c, const uint32_t* a,
                                      uint32_t b0, uint32_t b1) {
    asm volatile(
        "mma.sync.aligned.m16n8k16.row.col.f32.bf16.bf16.f32 "
        "{%0,%1,%2,%3}, {%4,%5,%6,%7}, {%8,%9}, {%0,%1,%2,%3};"
        : "+f"(c[0]), "+f"(c[1]), "+f"(c[2]), "+f"(c[3])
        : "r"(a[0]), "r"(a[1]), "r"(a[2]), "r"(a[3]), "r"(b0), "r"(b1));
}

__device__ __forceinline__ float bflo(uint32_t u) { return __uint_as_float(u << 16); }
__device__ __forceinline__ float bfhi(uint32_t u) { return __uint_as_float(u & 0xFFFF0000u); }

// ---------------- setup ----------------
__global__ void k_zero() {
    int i = blockIdx.x * blockDim.x + threadIdx.x;
    if (i < NN) { g_deg[i] = 0; g_fill[i] = 0; }
    if (i < NG * DD) g_pooled[i] = 0.f;
    if (i < NG) g_gcnt[i] = 0;
    if (i < 128) g_agg[i] = 0u;
}

// fused: degree count + bf16 feature copy + effective-weight prep
__global__ void k_pre(const float* __restrict__ feat, const int* __restrict__ dst,
                      const float* __restrict__ w11, const float* __restrict__ w21,
                      const float* __restrict__ w12, const float* __restrict__ w22) {
    int i = blockIdx.x * blockDim.x + threadIdx.x;
    if (i < NE) atomicAdd(&g_deg[dst[i]], 1);
    if (i < NN * DD / 4) {
        float4 v = __ldg((const float4*)feat + i);
        uint2 b;
        b.x = bf2pack(v.x, v.y);
        b.y = bf2pack(v.z, v.w);
        ((uint2*)g_fb)[i] = b;
    }
    if (i < DD * DD) {
        const float B1 = 0.6931471805599453f;  // log 2
        const float B2 = 0.4054651081081644f;  // log 1.5
        int n = i >> 7, k = i & 127;
        float ikn = (k == n) ? 1.f : 0.f;
        g_w1b[0][n * DD + k] = bf1(B1 * w11[k * DD + n] + (1.f - B1) * ikn);
        g_w2b[0][n * DD + k] = bf1(0.5f * (B1 * w21[k * DD + n] + (1.f - B1) * ikn));
        g_w1b[1][n * DD + k] = bf1(B2 * w12[k * DD + n] + (1.f - B2) * ikn);
        g_w2b[1][n * DD + k] = bf1(0.5f * (B2 * w22[k * DD + n] + (1.f - B2) * ikn));
    }
}

// fused scan: block-local scan + warp-parallel aggregate lookback + norm/gcnt
__global__ void k_scan(const int* __restrict__ gids) {
    __shared__ int s[1024];
    __shared__ int blockoff;
    int b = blockIdx.x, t = threadIdx.x;
    int i = b * 1024 + t;
    int v = (i < NN) ? g_deg[i] : 0;
    s[t] = v;
    __syncthreads();
    #pragma unroll
    for (int off = 1; off < 1024; off <<= 1) {
        int x = (t >= off) ? s[t - off] : 0;
        __syncthreads();
        s[t] += x;
        __syncthreads();
    }
    if (t == 1023)
        atomicExch(&g_agg[b], 0x80000000u | (unsigned)s[1023]);
    if (t < 32) {
        int sum = 0;
        for (int base = 0; base < b; base += 32) {
            int idx = base + t;
            unsigned val = 0;
            if (idx < b) {
                do { val = *(volatile unsigned*)&g_agg[idx]; }
                while (!(val & 0x80000000u));
            }
            sum += (int)(val & 0x7FFFFFFFu);
        }
        #pragma unroll
        for (int o = 16; o > 0; o >>= 1)
            sum += __shfl_down_sync(0xFFFFFFFFu, sum, o);
        if (t == 0) blockoff = sum;
    }
    __syncthreads();
    if (i < NN) {
        g_off[i] = blockoff + s[t] - v;
        g_norm[i] = rsqrtf((float)(v + 1));   // +1 self loop
        atomicAdd(&g_gcnt[gids[i]], 1);
    }
    if (i == NN) g_off[NN] = NE;
}

__global__ void k_fill(const int* __restrict__ src, const int* __restrict__ dst) {
    int i = blockIdx.x * blockDim.x + threadIdx.x;
    if (i < NE) {
        int d = dst[i];
        int p = g_off[d] + atomicAdd(&g_fill[d], 1);
        g_csr[p] = src[i];
    }
}

// ============ fused layer: SpMM (gather) -> smem A tile -> bf16 GEMM =======
// smem layout (96KB): A_spmm [0,32K) = 2 chunks x 16KB;
//   stage s (s=0,1): B at 32K + s*32K, F at 48K + s*32K.
// GEMM chunks: c0/c1 = A_spmm(hs) x W1e(ko 0/64); c2/c3 = f0 x W2e(ko 0/64).
// LAYER 0: epilogue writes bf16 x1. LAYER 1: epilogue pools into g_pooled.
template <int LAYER>
__global__ void __launch_bounds__(256, 2)
k_layer(const uint16_t* __restrict__ fin, const uint16_t* __restrict__ f0,
        const uint16_t* __restrict__ Bw1, const uint16_t* __restrict__ Bw2,
        const float* __restrict__ bias, uint16_t* __restrict__ xbout,
        const int* __restrict__ gids) {
    extern __shared__ char smem[];
    uint32_t sb = smem_u32(smem);
    int t = threadIdx.x, lane32 = t & 31, w = t >> 5;
    int R0 = blockIdx.x * 128;

    auto loadB = [&](int c) {
        uint32_t bB = sb + 32768u + (uint32_t)(c & 1) * 32768u;
        const uint16_t* B = (c < 2) ? Bw1 : Bw2;
        int ko = (c & 1) * 64;
        #pragma unroll
        for (int i = 0; i < 4; i++) {
            int idx = i * 256 + t;
            int r = idx >> 3, f4 = idx & 7;
            uint32_t off = r * 128 + ((f4 * 16) ^ ((r & 7) << 4));
            cpa16(bB + off, B + (size_t)r * DD + ko + f4 * 8);
        }
    };
    auto loadF = [&](int c) {   // c in {2,3}
        uint32_t fB = sb + 49152u + (uint32_t)(c & 1) * 32768u;
        int ko = (c & 1) * 64;
        #pragma unroll
        for (int i = 0; i < 4; i++) {
            int idx = i * 256 + t;
            int r = idx >> 3, f4 = idx & 7;
            int row = R0 + r; if (row >= NN) row = 0;
            uint32_t off = r * 128 + ((f4 * 16) ^ ((r & 7) << 4));
            cpa16(fB + off, f0 + (size_t)row * DD + ko + f4 * 8);
        }
    };

    // prologue: stream weights + f0 while spmm gathers
    loadB(0);
    asm volatile("cp.async.commit_group;" ::: "memory");   // G0
    loadB(1); loadF(2); loadF(3);
    asm volatile("cp.async.commit_group;" ::: "memory");   // G1

    // ---- SpMM phase: 16-lane groups, 8 rows each, into A_spmm smem ----
    {
        int grp = t >> 4, lane = t & 15;
        const uint4* F = (const uint4*)fin;
        #pragma unroll 1
        for (int local = grp; local < 128; local += 16) {
            int node = R0 + local;
            float acc[8] = {0.f, 0.f, 0.f, 0.f, 0.f, 0.f, 0.f, 0.f};
            if (node < NN) {
                float nrm = g_norm[node];
                uint4 a = __ldg(F + (size_t)node * 16 + lane);
                acc[0] = bflo(a.x) * nrm; acc[1] = bfhi(a.x) * nrm;
                acc[2] = bflo(a.y) * nrm; acc[3] = bfhi(a.y) * nrm;
                acc[4] = bflo(a.z) * nrm; acc[5] = bfhi(a.z) * nrm;
                acc[6] = bflo(a.w) * nrm; acc[7] = bfhi(a.w) * nrm;
                int beg = g_off[node], end = g_off[node + 1];
                int e = beg;
                for (; e + 4 <= end; e += 4) {
                    int s0 = __ldg(g_csr + e + 0), s1 = __ldg(g_csr + e + 1);
                    int s2 = __ldg(g_csr + e + 2), s3 = __ldg(g_csr + e + 3);
                    float n0 = __ldg(g_norm + s0), n1 = __ldg(g_norm + s1);
                    float n2 = __ldg(g_norm + s2), n3 = __ldg(g_norm + s3);
                    uint4 v0 = __ldg(F + (size_t)s0 * 16 + lane);
                    uint4 v1 = __ldg(F + (size_t)s1 * 16 + lane);
                    uint4 v2 = __ldg(F + (size_t)s2 * 16 + lane);
                    uint4 v3 = __ldg(F + (size_t)s3 * 16 + lane);
                    acc[0] = fmaf(n0, bflo(v0.x), acc[0]); acc[1] = fmaf(n0, bfhi(v0.x), acc[1]);
                    acc[2] = fmaf(n0, bflo(v0.y), acc[2]); acc[3] = fmaf(n0, bfhi(v0.y), acc[3]);
                    acc[4] = fmaf(n0, bflo(v0.z), acc[4]); acc[5] = fmaf(n0, bfhi(v0.z), acc[5]);
                    acc[6] = fmaf(n0, bflo(v0.w), acc[6]); acc[7] = fmaf(n0, bfhi(v0.w), acc[7]);
                    acc[0] = fmaf(n1, bflo(v1.x), acc[0]); acc[1] = fmaf(n1, bfhi(v1.x), acc[1]);
                    acc[2] = fmaf(n1, bflo(v1.y), acc[2]); acc[3] = fmaf(n1, bfhi(v1.y), acc[3]);
                    acc[4] = fmaf(n1, bflo(v1.z), acc[4]); acc[5] = fmaf(n1, bfhi(v1.z), acc[5]);
                    acc[6] = fmaf(n1, bflo(v1.w), acc[6]); acc[7] = fmaf(n1, bfhi(v1.w), acc[7]);
                    acc[0] = fmaf(n2, bflo(v2.x), acc[0]); acc[1] = fmaf(n2, bfhi(v2.x), acc[1]);
                    acc[2] = fmaf(n2, bflo(v2.y), acc[2]); acc[3] = fmaf(n2, bfhi(v2.y), acc[3]);
                    acc[4] = fmaf(n2, bflo(v2.z), acc[4]); acc[5] = fmaf(n2, bfhi(v2.z), acc[5]);
                    acc[6] = fmaf(n2, bflo(v2.w), acc[6]); acc[7] = fmaf(n2, bfhi(v2.w), acc[7]);
                    acc[0] = fmaf(n3, bflo(v3.x), acc[0]); acc[1] = fmaf(n3, bfhi(v3.x), acc[1]);
                    acc[2] = fmaf(n3, bflo(v3.y), acc[2]); acc[3] = fmaf(n3, bfhi(v3.y), acc[3]);
                    acc[4] = fmaf(n3, bflo(v3.z), acc[4]); acc[5] = fmaf(n3, bfhi(v3.z), acc[5]);
                    acc[6] = fmaf(n3, bflo(v3.w), acc[6]); acc[7] = fmaf(n3, bfhi(v3.w), acc[7]);
                }
                for (; e < end; e++) {
                    int s0 = __ldg(g_csr + e);
                    float n0 = __ldg(g_norm + s0);
                    uint4 v0 = __ldg(F + (size_t)s0 * 16 + lane);
                    acc[0] = fmaf(n0, bflo(v0.x), acc[0]); acc[1] = fmaf(n0, bfhi(v0.x), acc[1]);
                    acc[2] = fmaf(n0, bflo(v0.y), acc[2]); acc[3] = fmaf(n0, bfhi(v0.y), acc[3]);
                    acc[4] = fmaf(n0, bflo(v0.z), acc[4]); acc[5] = fmaf(n0, bfhi(v0.z), acc[5]);
                    acc[6] = fmaf(n0, bflo(v0.w), acc[6]); acc[7] = fmaf(n0, bfhi(v0.w), acc[7]);
                }
                float sc = 0.5f * nrm;
                #pragma unroll
                for (int q = 0; q < 8; q++) acc[q] *= sc;
            }
            uint4 o;
            o.x = bf2pack(acc[0], acc[1]);
            o.y = bf2pack(acc[2], acc[3]);
            o.z = bf2pack(acc[4], acc[5]);
            o.w = bf2pack(acc[6], acc[7]);
            // A_spmm swizzled store: chunk = lane>>3, unit f4 = lane&7
            uint32_t boff = (uint32_t)(lane >> 3) * 16384u + (uint32_t)local * 128u
                          + (uint32_t)((((lane & 7) * 16) ^ ((local & 7) << 4)));
            *(uint4*)(smem + boff) = o;
        }
    }

    // ---- GEMM phase ----
    int wm = (w & 3) * 32, wn = (w >> 2) * 64;
    float acc[2][8][4];
    #pragma unroll
    for (int mt = 0; mt < 2; mt++)
        #pragma unroll
        for (int j = 0; j < 8; j++)
            #pragma unroll
            for (int q = 0; q < 4; q++) acc[mt][j][q] = 0.f;

    int rA[2], rB[4];
    #pragma unroll
    for (int mt = 0; mt < 2; mt++)
        rA[mt] = wm + mt * 16 + (lane32 & 7) + ((lane32 >> 3) & 1) * 8;
    #pragma unroll
    for (int nt = 0; nt < 4; nt++)
        rB[nt] = wn + nt * 16 + (lane32 & 7) + ((lane32 >> 4) & 1) * 8;
    uint32_t aH = ((lane32 >> 4) & 1) * 16;
    uint32_t bH = ((lane32 >> 3) & 1) * 16;

    #pragma unroll
    for (int c = 0; c < 4; c++) {
        if (c < 3) asm volatile("cp.async.wait_group 1;" ::: "memory");
        else       asm volatile("cp.async.wait_group 0;" ::: "memory");
        __syncthreads();

        uint32_t aB = (c < 2) ? (sb + (uint32_t)c * 16384u)
                              : (sb + 49152u + (uint32_t)(c & 1) * 32768u);
        uint32_t bB = sb + 32768u + (uint32_t)(c & 1) * 32768u;
        #pragma unroll
        for (int kk = 0; kk < 4; kk++) {
            uint32_t a[2][4], b[4][4];
            #pragma unroll
            for (int mt = 0; mt < 2; mt++)
                ldsm4(a[mt], aB + rA[mt] * 128 +
                              (((uint32_t)(kk * 32) + aH) ^ ((rA[mt] & 7) << 4)));
            #pragma unroll
            for (int nt = 0; nt < 4; nt++)
                ldsm4(b[nt], bB + rB[nt] * 128 +
                              (((uint32_t)(kk * 32) + bH) ^ ((rB[nt] & 7) << 4)));
            #pragma unroll
            for (int mt = 0; mt < 2; mt++)
                #pragma unroll
                for (int nt = 0; nt < 4; nt++) {
                    mma16(acc[mt][2 * nt + 0], a[mt], b[nt][0], b[nt][1]);
                    mma16(acc[mt][2 * nt + 1], a[mt], b[nt][2], b[nt][3]);
                }
        }
        __syncthreads();
        if (c + 2 < 4) {
            loadB(c + 2);
            asm volatile("cp.async.commit_group;" ::: "memory");
        }
    }

    // ---- epilogue ----
    if (LAYER == 0) {
        #pragma unroll
        for (int mt = 0; mt < 2; mt++) {
            int row0 = R0 + wm + mt * 16 + (lane32 >> 2);
            #pragma unroll
            for (int j = 0; j < 8; j++) {
                int col = wn + j * 8 + (lane32 & 3) * 2;
                float2 bb = *(const float2*)(bias + col);
                float v0 = fmaxf(acc[mt][j][0] + bb.x, 0.f);
                float v1 = fmaxf(acc[mt][j][1] + bb.y, 0.f);
                float v2 = fmaxf(acc[mt][j][2] + bb.x, 0.f);
                float v3 = fmaxf(acc[mt][j][3] + bb.y, 0.f);
                if (row0 < NN)
                    *(uint32_t*)(xbout + (size_t)row0 * DD + col) = bf2pack(v0, v1);
                if (row0 + 8 < NN)
                    *(uint32_t*)(xbout + (size_t)(row0 + 8) * DD + col) = bf2pack(v2, v3);
            }
        }
    } else {
        // pooled epilogue: rows r0, r0+8, r0+16, r0+24 per thread
        int r0 = R0 + wm + (lane32 >> 2);
        int ra = r0, rb = r0 + 8, rc = r0 + 16, rd = r0 + 24;
        bool va = ra < NN, vb = rb < NN, vc = rc < NN, vd = rd < NN;
        if (va) {
            int ga = __ldg(gids + ra);
            int gb = vb ? __ldg(gids + rb) : ga;
            int gc = vc ? __ldg(gids + rc) : ga;
            int gd = vd ? __ldg(gids + rd) : ga;
            bool same = (ga == gb) && (gb == gc) && (gc == gd);
            #pragma unroll
            for (int j = 0; j < 8; j++) {
                int col = wn + j * 8 + (lane32 & 3) * 2;
                float2 bb = *(const float2*)(bias + col);
                #pragma unroll
                for (int q = 0; q < 2; q++) {
                    float bq = q ? bb.y : bb.x;
                    float u0 = va ? fmaxf(acc[0][j][q + 0] + bq, 0.f) : 0.f;
                    float u1 = vb ? fmaxf(acc[0][j][q + 2] + bq, 0.f) : 0.f;
                    float u2 = vc ? fmaxf(acc[1][j][q + 0] + bq, 0.f) : 0.f;
                    float u3 = vd ? fmaxf(acc[1][j][q + 2] + bq, 0.f) : 0.f;
                    if (same) {
                        atomicAdd(&g_pooled[ga * DD + col + q], u0 + u1 + u2 + u3);
                    } else {
                        atomicAdd(&g_pooled[ga * DD + col + q], u0);
                        if (vb) atomicAdd(&g_pooled[gb * DD + col + q], u1);
                        if (vc) atomicAdd(&g_pooled[gc * DD + col + q], u2);
                        if (vd) atomicAdd(&g_pooled[gd * DD + col + q], u3);
                    }
                }
            }
        }
    }
}

// ---------------- final MLP ----------------
__global__ void k_mlp(const float* __restrict__ d1w, const float* __restrict__ d1b,
                      const float* __restrict__ d2w, const float* __restrict__ d2b,
                      float* __restrict__ out) {
    int b = threadIdx.x;
    if (b >= NG) return;
    float inv = 1.f / fmaxf((float)g_gcnt[b], 1.f);
    float h[PHH];
    #pragma unroll
    for (int p = 0; p < PHH; p++) h[p] = __ldg(d1b + p);
    for (int c = 0; c < DD; c++) {
        float a = g_pooled[b * DD + c] * inv;
        #pragma unroll
        for (int p = 0; p < PHH; p++)
            h[p] = fmaf(a, __ldg(d1w + c * PHH + p), h[p]);
    }
    float z = __ldg(d2b);
    #pragma unroll
    for (int p = 0; p < PHH; p++)
        z = fmaf(fmaxf(h[p], 0.f), __ldg(d2w + p), z);
    out[b] = 1.f / (1.f + expf(-z));
}

// ---------------- launch ----------------
extern "C" void kernel_launch(void* const* d_in, const int* in_sizes, int n_in,
                              void* d_out, int out_size) {
    const float* feature = (const float*)d_in[0];
    const int*   src     = (const int*)d_in[1];
    const int*   dst     = (const int*)d_in[2];
    const int*   gids    = (const int*)d_in[3];
    const float* w1_1    = (const float*)d_in[4];
    const float* w2_1    = (const float*)d_in[5];
    const float* b_1     = (const float*)d_in[6];
    const float* w1_2    = (const float*)d_in[7];
    const float* w2_2    = (const float*)d_in[8];
    const float* b_2     = (const float*)d_in[9];
    const float* d1w     = (const float*)d_in[10];
    const float* d1b     = (const float*)d_in[11];
    const float* d2w     = (const float*)d_in[12];
    const float* d2b     = (const float*)d_in[13];
    float* out = (float*)d_out;

    uint16_t *fb_p = nullptr, *xb_p = nullptr, *w1b_p = nullptr, *w2b_p = nullptr;
    cudaGetSymbolAddress((void**)&fb_p,  g_fb);
    cudaGetSymbolAddress((void**)&xb_p,  g_xb);
    cudaGetSymbolAddress((void**)&w1b_p, g_w1b);
    cudaGetSymbolAddress((void**)&w2b_p, g_w2b);

    const int SMEM_LAYER = 98304;   // A_spmm 32KB + 2 stages x (B 16KB + F 16KB)
    cudaFuncSetAttribute(k_layer<0>, cudaFuncAttributeMaxDynamicSharedMemorySize, SMEM_LAYER);
    cudaFuncSetAttribute(k_layer<1>, cudaFuncAttributeMaxDynamicSharedMemorySize, SMEM_LAYER);

    k_zero<<<(NN + 255) / 256, 256>>>();
    k_pre<<<(NN * DD / 4 + 255) / 256, 256>>>(feature, dst, w1_1, w2_1, w1_2, w2_2);
    k_scan<<<NSB, 1024>>>(gids);
    k_fill<<<(NE + 255) / 256, 256>>>(src, dst);

    // layer 1: gather from feature(bf16), f0 = feature(bf16), write bf16 x1
    k_layer<0><<<NTILES, 256, SMEM_LAYER>>>(fb_p, fb_p, w1b_p, w2b_p, b_1, xb_p, gids);
    // layer 2: gather from x1(bf16), f0 = feature(bf16), pool into g_pooled
    k_layer<1><<<NTILES, 256, SMEM_LAYER>>>(xb_p, fb_p,
                                            w1b_p + DD * DD, w2b_p + DD * DD, b_2,
                                            nullptr, gids);
    // decoder
    k_mlp<<<1, 64>>>(d1w, d1b, d2w, d2b, out);
}

// round 8
// speedup vs baseline: 1.1353x; 1.1353x over previous
#include <cuda_runtime.h>
#include <cuda_bf16.h>
#include <math.h>
#include <stdint.h>

#define NN  100000
#define NE  1600000
#define DD  128
#define NG  64
#define PHH 32
#define NTILES 782   // ceil(NN/128)
#define NSB 98       // scan blocks

// ---------------- device scratch (no allocations allowed) ----------------
__device__ int      g_deg[NN];
__device__ int      g_off[NN + 1];
__device__ int      g_fill[NN];
__device__ int      g_csr[NE];
__device__ unsigned g_agg[128];            // lookback aggregates (bit31 = valid)
__device__ int      g_gcnt[NG];
__device__ float    g_norm[NN];
__device__ float    g_pooled[NG * DD];
__device__ uint16_t g_fb[NN * DD];         // bf16 feature, unscaled (GEMM f0)
__device__ uint16_t g_fs[NN * DD];         // bf16 norm⊙feature (L1 gather)
__device__ uint16_t g_hb[NN * DD];         // bf16 hs (GEMM A operand)
__device__ uint16_t g_xb[NN * DD];         // bf16 norm⊙x1 (L2 gather)
__device__ uint16_t g_w1b[2][DD * DD];     // effective W1 per layer, [n][k], bf16
__device__ uint16_t g_w2b[2][DD * DD];     // effective W2 (x0.5) per layer, bf16

// ---------------- helpers ----------------
__device__ __forceinline__ uint32_t smem_u32(const void* p) {
    uint32_t a;
    asm("{ .reg .u64 t; cvta.to.shared.u64 t, %1; cvt.u32.u64 %0, t; }"
        : "=r"(a) : "l"(p));
    return a;
}

__device__ __forceinline__ uint32_t bf2pack(float lo, float hi) {
    uint32_t p;
    asm("cvt.rn.bf16x2.f32 %0, %1, %2;" : "=r"(p) : "f"(hi), "f"(lo));
    return p;
}

__device__ __forceinline__ uint16_t bf1(float v) {
    return (uint16_t)(bf2pack(v, 0.f) & 0xFFFFu);
}

__device__ __forceinline__ void cpa16(uint32_t dst, const void* src) {
    asm volatile("cp.async.cg.shared.global [%0], [%1], 16;"
                 :: "r"(dst), "l"(src) : "memory");
}

__device__ __forceinline__ void ldsm4(uint32_t* r, uint32_t addr) {
    asm volatile("ldmatrix.sync.aligned.m8n8.x4.shared.b16 {%0,%1,%2,%3}, [%4];"
                 : "=r"(r[0]), "=r"(r[1]), "=r"(r[2]), "=r"(r[3]) : "r"(addr));
}

__device__ __forceinline__ void mma16(float* c, const uint32_t* a,
                                      uint32_t b0, uint32_t b1) {
    asm volatile(
        "mma.sync.aligned.m16n8k16.row.col.f32.bf16.bf16.f32 "
        "{%0,%1,%2,%3}, {%4,%5,%6,%7}, {%8,%9}, {%0,%1,%2,%3};"
        : "+f"(c[0]), "+f"(c[1]), "+f"(c[2]), "+f"(c[3])
        : "r"(a[0]), "r"(a[1]), "r"(a[2]), "r"(a[3]), "r"(b0), "r"(b1));
}

__device__ __forceinline__ float bflo(uint32_t u) { return __uint_as_float(u << 16); }
__device__ __forceinline__ float bfhi(uint32_t u) { return __uint_as_float(u & 0xFFFF0000u); }

// ---------------- setup ----------------
__global__ void k_zero() {
    int i = blockIdx.x * blockDim.x + threadIdx.x;
    if (i < NN) { g_deg[i] = 0; g_fill[i] = 0; }
    if (i < NG * DD) g_pooled[i] = 0.f;
    if (i < NG) g_gcnt[i] = 0;
    if (i < 128) g_agg[i] = 0u;
}

// fused: degree count + bf16 feature copy + effective-weight prep
__global__ void k_pre(const float* __restrict__ feat, const int* __restrict__ dst,
                      const float* __restrict__ w11, const float* __restrict__ w21,
                      const float* __restrict__ w12, const float* __restrict__ w22) {
    int i = blockIdx.x * blockDim.x + threadIdx.x;
    if (i < NE) atomicAdd(&g_deg[dst[i]], 1);
    if (i < NN * DD / 4) {
        float4 v = __ldg((const float4*)feat + i);
        uint2 b;
        b.x = bf2pack(v.x, v.y);
        b.y = bf2pack(v.z, v.w);
        ((uint2*)g_fb)[i] = b;
    }
    if (i < DD * DD) {
        const float B1 = 0.6931471805599453f;  // log 2
        const float B2 = 0.4054651081081644f;  // log 1.5
        int n = i >> 7, k = i & 127;
        float ikn = (k == n) ? 1.f : 0.f;
        g_w1b[0][n * DD + k] = bf1(B1 * w11[k * DD + n] + (1.f - B1) * ikn);
        g_w2b[0][n * DD + k] = bf1(0.5f * (B1 * w21[k * DD + n] + (1.f - B1) * ikn));
        g_w1b[1][n * DD + k] = bf1(B2 * w12[k * DD + n] + (1.f - B2) * ikn);
        g_w2b[1][n * DD + k] = bf1(0.5f * (B2 * w22[k * DD + n] + (1.f - B2) * ikn));
    }
}

// fused scan: block-local scan + warp-parallel aggregate lookback + norm/gcnt
__global__ void k_scan(const int* __restrict__ gids) {
    __shared__ int s[1024];
    __shared__ int blockoff;
    int b = blockIdx.x, t = threadIdx.x;
    int i = b * 1024 + t;
    int v = (i < NN) ? g_deg[i] : 0;
    s[t] = v;
    __syncthreads();
    #pragma unroll
    for (int off = 1; off < 1024; off <<= 1) {
        int x = (t >= off) ? s[t - off] : 0;
        __syncthreads();
        s[t] += x;
        __syncthreads();
    }
    if (t == 1023)
        atomicExch(&g_agg[b], 0x80000000u | (unsigned)s[1023]);
    if (t < 32) {
        int sum = 0;
        for (int base = 0; base < b; base += 32) {
            int idx = base + t;
            unsigned val = 0;
            if (idx < b) {
                do { val = *(volatile unsigned*)&g_agg[idx]; }
                while (!(val & 0x80000000u));
            }
            sum += (int)(val & 0x7FFFFFFFu);
        }
        #pragma unroll
        for (int o = 16; o > 0; o >>= 1)
            sum += __shfl_down_sync(0xFFFFFFFFu, sum, o);
        if (t == 0) blockoff = sum;
    }
    __syncthreads();
    if (i < NN) {
        g_off[i] = blockoff + s[t] - v;
        g_norm[i] = rsqrtf((float)(v + 1));   // +1 self loop
        atomicAdd(&g_gcnt[gids[i]], 1);
    }
    if (i == NN) g_off[NN] = NE;
}

// fused: CSR fill + scaled-feature (norm ⊙ feature, bf16) for the L1 gather
__global__ void k_fill(const int* __restrict__ src, const int* __restrict__ dst) {
    int i = blockIdx.x * blockDim.x + threadIdx.x;
    if (i < NE) {
        int d = dst[i];
        int p = g_off[d] + atomicAdd(&g_fill[d], 1);
        g_csr[p] = src[i];
    }
    if (i < NN * DD / 4) {
        int node = i >> 5;                  // 32 uint2 per row
        float nrm = g_norm[node];
        uint2 b = ((const uint2*)g_fb)[i];
        uint2 o;
        o.x = bf2pack(bflo(b.x) * nrm, bfhi(b.x) * nrm);
        o.y = bf2pack(bflo(b.y) * nrm, bfhi(b.y) * nrm);
        ((uint2*)g_fs)[i] = o;
    }
}

// ---- SpMM (pre-scaled bf16 gather): out = bf16(0.5*nrm*(x̃[n] + Σ x̃[src]))
// 16-lane node groups (uint4 = 8 bf16/lane), 8-edge unroll, pure adds.
__global__ void k_spmm(const uint16_t* __restrict__ fin, uint16_t* __restrict__ fout) {
    int gt = blockIdx.x * blockDim.x + threadIdx.x;
    int node = gt >> 4, lane = gt & 15;
    if (node >= NN) return;
    const uint4* F = (const uint4*)fin;   // row = 16 x uint4
    uint4 a = __ldg(F + (size_t)node * 16 + lane);   // self loop (pre-scaled)
    float acc[8];
    acc[0] = bflo(a.x); acc[1] = bfhi(a.x);
    acc[2] = bflo(a.y); acc[3] = bfhi(a.y);
    acc[4] = bflo(a.z); acc[5] = bfhi(a.z);
    acc[6] = bflo(a.w); acc[7] = bfhi(a.w);

    int beg = g_off[node], end = g_off[node + 1];
    int e = beg;
    for (; e + 8 <= end; e += 8) {
        uint4 v[8];
        #pragma unroll
        for (int j = 0; j < 8; j++) {
            int s = __ldg(g_csr + e + j);
            v[j] = __ldg(F + (size_t)s * 16 + lane);
        }
        #pragma unroll
        for (int j = 0; j < 8; j++) {
            acc[0] += bflo(v[j].x); acc[1] += bfhi(v[j].x);
            acc[2] += bflo(v[j].y); acc[3] += bfhi(v[j].y);
            acc[4] += bflo(v[j].z); acc[5] += bfhi(v[j].z);
            acc[6] += bflo(v[j].w); acc[7] += bfhi(v[j].w);
        }
    }
    for (; e < end; e++) {
        int s = __ldg(g_csr + e);
        uint4 v0 = __ldg(F + (size_t)s * 16 + lane);
        acc[0] += bflo(v0.x); acc[1] += bfhi(v0.x);
        acc[2] += bflo(v0.y); acc[3] += bfhi(v0.y);
        acc[4] += bflo(v0.z); acc[5] += bfhi(v0.z);
        acc[6] += bflo(v0.w); acc[7] += bfhi(v0.w);
    }
    float sc = 0.5f * g_norm[node];
    uint4 o;
    o.x = bf2pack(acc[0] * sc, acc[1] * sc);
    o.y = bf2pack(acc[2] * sc, acc[3] * sc);
    o.z = bf2pack(acc[4] * sc, acc[5] * sc);
    o.w = bf2pack(acc[6] * sc, acc[7] * sc);
    ((uint4*)fout)[(size_t)node * 16 + lane] = o;
}

// ---- bf16 mma.sync GEMM: relu(hs@W1e + f0@W2e + b) ------------------------
// BM=128, BN=128, K=256 (hs|f0), BK=64 bf16 (128B rows), 4 chunks,
// 8 warps (warp tile 32x64), 2-stage cp.async pipeline, SW128 swizzle.
// MODE 0: write bf16 norm⊙x1 (feeds L2 gather). MODE 1: pool into g_pooled.
template <int MODE>
__global__ void __launch_bounds__(256, 2)
k_mma(const uint16_t* __restrict__ Ahs, const uint16_t* __restrict__ Af0,
      const uint16_t* __restrict__ Bw1, const uint16_t* __restrict__ Bw2,
      const float* __restrict__ bias, uint16_t* __restrict__ xbout,
      const int* __restrict__ gids) {
    extern __shared__ float smem[];   // 2 stages x (A 16KB + B 16KB)
    uint32_t sb = smem_u32(smem);
    int t = threadIdx.x, lane = t & 31, w = t >> 5;
    int wm = (w & 3) * 32, wn = (w >> 2) * 64;
    int R0 = blockIdx.x * 128;

    float acc[2][8][4];
    #pragma unroll
    for (int mt = 0; mt < 2; mt++)
        #pragma unroll
        for (int j = 0; j < 8; j++)
            #pragma unroll
            for (int q = 0; q < 4; q++) acc[mt][j][q] = 0.f;

    auto load_chunk = [&](int c) {
        int s = c & 1;
        uint32_t aB = sb + s * 32768;
        uint32_t bB = aB + 16384;
        const uint16_t* A = (c < 2) ? Ahs : Af0;
        const uint16_t* B = (c < 2) ? Bw1 : Bw2;
        int ko = (c & 1) * 64;
        #pragma unroll
        for (int i = 0; i < 4; i++) {
            int idx = i * 256 + t;
            int r = idx >> 3, f4 = idx & 7;
            int row = R0 + r; if (row >= NN) row = 0;
            uint32_t off = r * 128 + ((f4 * 16) ^ ((r & 7) << 4));
            cpa16(aB + off, A + (size_t)row * DD + ko + f4 * 8);
            cpa16(bB + off, B + (size_t)r * DD + ko + f4 * 8);
        }
        asm volatile("cp.async.commit_group;" ::: "memory");
    };

    load_chunk(0);
    load_chunk(1);

    int rA[2], rB[4];
    #pragma unroll
    for (int mt = 0; mt < 2; mt++)
        rA[mt] = wm + mt * 16 + (lane & 7) + ((lane >> 3) & 1) * 8;
    #pragma unroll
    for (int nt = 0; nt < 4; nt++)
        rB[nt] = wn + nt * 16 + (lane & 7) + ((lane >> 4) & 1) * 8;
    uint32_t aH = ((lane >> 4) & 1) * 16;
    uint32_t bH = ((lane >> 3) & 1) * 16;

    for (int c = 0; c < 4; c++) {
        int s = c & 1;
        if (c < 3) asm volatile("cp.async.wait_group 1;" ::: "memory");
        else       asm volatile("cp.async.wait_group 0;" ::: "memory");
        __syncthreads();

        uint32_t aB = sb + s * 32768;
        uint32_t bB = aB + 16384;
        #pragma unroll
        for (int kk = 0; kk < 4; kk++) {
            uint32_t a[2][4], b[4][4];
            #pragma unroll
            for (int mt = 0; mt < 2; mt++)
                ldsm4(a[mt], aB + rA[mt] * 128 +
                              (((uint32_t)(kk * 32) + aH) ^ ((rA[mt] & 7) << 4)));
            #pragma unroll
            for (int nt = 0; nt < 4; nt++)
                ldsm4(b[nt], bB + rB[nt] * 128 +
                              (((uint32_t)(kk * 32) + bH) ^ ((rB[nt] & 7) << 4)));
            #pragma unroll
            for (int mt = 0; mt < 2; mt++)
                #pragma unroll
                for (int nt = 0; nt < 4; nt++) {
                    mma16(acc[mt][2 * nt + 0], a[mt], b[nt][0], b[nt][1]);
                    mma16(acc[mt][2 * nt + 1], a[mt], b[nt][2], b[nt][3]);
                }
        }
        __syncthreads();
        if (c + 2 < 4) load_chunk(c + 2);
    }

    if (MODE == 0) {
        // epilogue: bias + relu + norm-prescale + bf16 pack
        #pragma unroll
        for (int mt = 0; mt < 2; mt++) {
            int row0 = R0 + wm + mt * 16 + (lane >> 2);
            float nr0 = (row0 < NN) ? g_norm[row0] : 0.f;
            float nr1 = (row0 + 8 < NN) ? g_norm[row0 + 8] : 0.f;
            #pragma unroll
            for (int j = 0; j < 8; j++) {
                int col = wn + j * 8 + (lane & 3) * 2;
                float2 bb = *(const float2*)(bias + col);
                float v0 = fmaxf(acc[mt][j][0] + bb.x, 0.f) * nr0;
                float v1 = fmaxf(acc[mt][j][1] + bb.y, 0.f) * nr0;
                float v2 = fmaxf(acc[mt][j][2] + bb.x, 0.f) * nr1;
                float v3 = fmaxf(acc[mt][j][3] + bb.y, 0.f) * nr1;
                if (row0 < NN)
                    *(uint32_t*)(xbout + (size_t)row0 * DD + col) = bf2pack(v0, v1);
                if (row0 + 8 < NN)
                    *(uint32_t*)(xbout + (size_t)(row0 + 8) * DD + col) = bf2pack(v2, v3);
            }
        }
    } else {
        // pooled epilogue: rows r0, r0+8, r0+16, r0+24 per thread
        int r0 = R0 + wm + (lane >> 2);
        int ra = r0, rb = r0 + 8, rc = r0 + 16, rd = r0 + 24;
        bool va = ra < NN, vb = rb < NN, vc = rc < NN, vd = rd < NN;
        if (va) {
            int ga = __ldg(gids + ra);
            int gb = vb ? __ldg(gids + rb) : ga;
            int gc = vc ? __ldg(gids + rc) : ga;
            int gd = vd ? __ldg(gids + rd) : ga;
            bool same = (ga == gb) && (gb == gc) && (gc == gd);
            #pragma unroll
            for (int j = 0; j < 8; j++) {
                int col = wn + j * 8 + (lane & 3) * 2;
                float2 bb = *(const float2*)(bias + col);
                #pragma unroll
                for (int q = 0; q < 2; q++) {
                    float bq = q ? bb.y : bb.x;
                    float u0 = va ? fmaxf(acc[0][j][q + 0] + bq, 0.f) : 0.f;
                    float u1 = vb ? fmaxf(acc[0][j][q + 2] + bq, 0.f) : 0.f;
                    float u2 = vc ? fmaxf(acc[1][j][q + 0] + bq, 0.f) : 0.f;
                    float u3 = vd ? fmaxf(acc[1][j][q + 2] + bq, 0.f) : 0.f;
                    if (same) {
                        atomicAdd(&g_pooled[ga * DD + col + q], u0 + u1 + u2 + u3);
                    } else {
                        atomicAdd(&g_pooled[ga * DD + col + q], u0);
                        if (vb) atomicAdd(&g_pooled[gb * DD + col + q], u1);
                        if (vc) atomicAdd(&g_pooled[gc * DD + col + q], u2);
                        if (vd) atomicAdd(&g_pooled[gd * DD + col + q], u3);
                    }
                }
            }
        }
    }
}

// ---------------- final MLP ----------------
__global__ void k_mlp(const float* __restrict__ d1w, const float* __restrict__ d1b,
                      const float* __restrict__ d2w, const float* __restrict__ d2b,
                      float* __restrict__ out) {
    int b = threadIdx.x;
    if (b >= NG) return;
    float inv = 1.f / fmaxf((float)g_gcnt[b], 1.f);
    float h[PHH];
    #pragma unroll
    for (int p = 0; p < PHH; p++) h[p] = __ldg(d1b + p);
    for (int c = 0; c < DD; c++) {
        float a = g_pooled[b * DD + c] * inv;
        #pragma unroll
        for (int p = 0; p < PHH; p++)
            h[p] = fmaf(a, __ldg(d1w + c * PHH + p), h[p]);
    }
    float z = __ldg(d2b);
    #pragma unroll
    for (int p = 0; p < PHH; p++)
        z = fmaf(fmaxf(h[p], 0.f), __ldg(d2w + p), z);
    out[b] = 1.f / (1.f + expf(-z));
}

// ---------------- launch ----------------
extern "C" void kernel_launch(void* const* d_in, const int* in_sizes, int n_in,
                              void* d_out, int out_size) {
    const float* feature = (const float*)d_in[0];
    const int*   src     = (const int*)d_in[1];
    const int*   dst     = (const int*)d_in[2];
    const int*   gids    = (const int*)d_in[3];
    const float* w1_1    = (const float*)d_in[4];
    const float* w2_1    = (const float*)d_in[5];
    const float* b_1     = (const float*)d_in[6];
    const float* w1_2    = (const float*)d_in[7];
    const float* w2_2    = (const float*)d_in[8];
    const float* b_2     = (const float*)d_in[9];
    const float* d1w     = (const float*)d_in[10];
    const float* d1b     = (const float*)d_in[11];
    const float* d2w     = (const float*)d_in[12];
    const float* d2b     = (const float*)d_in[13];
    float* out = (float*)d_out;

    uint16_t *fb_p = nullptr, *fs_p = nullptr, *hb_p = nullptr, *xb_p = nullptr;
    uint16_t *w1b_p = nullptr, *w2b_p = nullptr;
    cudaGetSymbolAddress((void**)&fb_p,  g_fb);
    cudaGetSymbolAddress((void**)&fs_p,  g_fs);
    cudaGetSymbolAddress((void**)&hb_p,  g_hb);
    cudaGetSymbolAddress((void**)&xb_p,  g_xb);
    cudaGetSymbolAddress((void**)&w1b_p, g_w1b);
    cudaGetSymbolAddress((void**)&w2b_p, g_w2b);

    const int SMEM_MMA = 65536;   // 2 stages x (A 16KB + B 16KB)
    cudaFuncSetAttribute(k_mma<0>, cudaFuncAttributeMaxDynamicSharedMemorySize, SMEM_MMA);
    cudaFuncSetAttribute(k_mma<1>, cudaFuncAttributeMaxDynamicSharedMemorySize, SMEM_MMA);

    k_zero<<<(NN + 255) / 256, 256>>>();
    k_pre<<<(NN * DD / 4 + 255) / 256, 256>>>(feature, dst, w1_1, w2_1, w1_2, w2_2);
    k_scan<<<NSB, 1024>>>(gids);
    k_fill<<<(NN * DD / 4 + 255) / 256, 256>>>(src, dst);

    // layer 1: spmm gathers norm⊙feature (g_fs) -> hs (g_hb);
    //          gemm (hb, fb) -> norm⊙x1 (g_xb)
    k_spmm<<<(NN * 16 + 255) / 256, 256>>>(fs_p, hb_p);
    k_mma<0><<<NTILES, 256, SMEM_MMA>>>(hb_p, fb_p, w1b_p, w2b_p, b_1, xb_p, gids);
    // layer 2: spmm gathers norm⊙x1 (g_xb) -> hs (g_hb);
    //          gemm (hb, fb) pools directly into g_pooled
    k_spmm<<<(NN * 16 + 255) / 256, 256>>>(xb_p, hb_p);
    k_mma<1><<<NTILES, 256, SMEM_MMA>>>(hb_p, fb_p,
                                        w1b_p + DD * DD, w2b_p + DD * DD, b_2,
                                        nullptr, gids);
    // decoder
    k_mlp<<<1, 64>>>(d1w, d1b, d2w, d2b, out);
}

// round 9
// speedup vs baseline: 1.1911x; 1.0492x over previous
#include <cuda_runtime.h>
#include <cuda_bf16.h>
#include <math.h>
#include <stdint.h>

#define NN  100000
#define NE  1600000
#define DD  128
#define NG  64
#define PHH 32
#define NTILES 782   // ceil(NN/128)
#define NSB 98       // scan blocks

// ---------------- device scratch (no allocations allowed) ----------------
__device__ int      g_deg[NN];
__device__ int      g_off[NN + 1];
__device__ int      g_fill[NN];
__device__ int      g_csr[NE];
__device__ unsigned g_agg[128];            // lookback aggregates (bit31 = valid)
__device__ int      g_gcnt[NG];
__device__ float    g_norm[NN];
__device__ float    g_pooled[NG * DD];
__device__ uint16_t g_fb[NN * DD];         // bf16 feature, unscaled (GEMM f0)
__device__ uint8_t  g_fs[NN * DD];         // fp8 norm⊙feature (L1 gather), 12.8MB
__device__ uint8_t  g_xs[NN * DD];         // fp8 norm⊙x1 (L2 gather), 12.8MB
__device__ uint16_t g_hb[NN * DD];         // bf16 hs (GEMM A operand)
__device__ uint16_t g_w1b[2][DD * DD];     // effective W1 per layer, [n][k], bf16
__device__ uint16_t g_w2b[2][DD * DD];     // effective W2 (x0.5) per layer, bf16

// ---------------- helpers ----------------
__device__ __forceinline__ uint32_t smem_u32(const void* p) {
    uint32_t a;
    asm("{ .reg .u64 t; cvta.to.shared.u64 t, %1; cvt.u32.u64 %0, t; }"
        : "=r"(a) : "l"(p));
    return a;
}

__device__ __forceinline__ uint32_t bf2pack(float lo, float hi) {
    uint32_t p;
    asm("cvt.rn.bf16x2.f32 %0, %1, %2;" : "=r"(p) : "f"(hi), "f"(lo));
    return p;
}

__device__ __forceinline__ uint16_t bf1(float v) {
    return (uint16_t)(bf2pack(v, 0.f) & 0xFFFFu);
}

// pack 2 floats -> e4m3x2 (lo in low byte)
__device__ __forceinline__ uint16_t fp8pack(float lo, float hi) {
    uint16_t r;
    asm("cvt.rn.satfinite.e4m3x2.f32 %0, %1, %2;" : "=h"(r) : "f"(hi), "f"(lo));
    return r;
}

// 4 fp8 (one u32) -> two half2
__device__ __forceinline__ void fp8x4_to_h2x2(uint32_t w, uint32_t& h01, uint32_t& h23) {
    asm("{ .reg .b16 lo, hi;\n\t"
        "mov.b32 {lo, hi}, %2;\n\t"
        "cvt.rn.f16x2.e4m3x2 %0, lo;\n\t"
        "cvt.rn.f16x2.e4m3x2 %1, hi; }"
        : "=r"(h01), "=r"(h23) : "r"(w));
}

__device__ __forceinline__ uint32_t hadd2(uint32_t a, uint32_t b) {
    uint32_t r;
    asm("add.f16x2 %0, %1, %2;" : "=r"(r) : "r"(a), "r"(b));
    return r;
}

__device__ __forceinline__ float2 h2f(uint32_t h) {
    float2 f;
    asm("{ .reg .b16 lo, hi;\n\t"
        "mov.b32 {lo, hi}, %2;\n\t"
        "cvt.f32.f16 %0, lo;\n\t"
        "cvt.f32.f16 %1, hi; }"
        : "=f"(f.x), "=f"(f.y) : "r"(h));
    return f;
}

__device__ __forceinline__ void cpa16(uint32_t dst, const void* src) {
    asm volatile("cp.async.cg.shared.global [%0], [%1], 16;"
                 :: "r"(dst), "l"(src) : "memory");
}

__device__ __forceinline__ void ldsm4(uint32_t* r, uint32_t addr) {
    asm volatile("ldmatrix.sync.aligned.m8n8.x4.shared.b16 {%0,%1,%2,%3}, [%4];"
                 : "=r"(r[0]), "=r"(r[1]), "=r"(r[2]), "=r"(r[3]) : "r"(addr));
}

__device__ __forceinline__ void mma16(float* c, const uint32_t* a,
                                      uint32_t b0, uint32_t b1) {
    asm volatile(
        "mma.sync.aligned.m16n8k16.row.col.f32.bf16.bf16.f32 "
        "{%0,%1,%2,%3}, {%4,%5,%6,%7}, {%8,%9}, {%0,%1,%2,%3};"
        : "+f"(c[0]), "+f"(c[1]), "+f"(c[2]), "+f"(c[3])
        : "r"(a[0]), "r"(a[1]), "r"(a[2]), "r"(a[3]), "r"(b0), "r"(b1));
}

__device__ __forceinline__ float bflo(uint32_t u) { return __uint_as_float(u << 16); }
__device__ __forceinline__ float bfhi(uint32_t u) { return __uint_as_float(u & 0xFFFF0000u); }

// ---------------- setup ----------------
__global__ void k_zero() {
    int i = blockIdx.x * blockDim.x + threadIdx.x;
    if (i < NN) { g_deg[i] = 0; g_fill[i] = 0; }
    if (i < NG * DD) g_pooled[i] = 0.f;
    if (i < NG) g_gcnt[i] = 0;
    if (i < 128) g_agg[i] = 0u;
}

// fused: degree count + bf16 feature copy + effective-weight prep
__global__ void k_pre(const float* __restrict__ feat, const int* __restrict__ dst,
                      const float* __restrict__ w11, const float* __restrict__ w21,
                      const float* __restrict__ w12, const float* __restrict__ w22) {
    int i = blockIdx.x * blockDim.x + threadIdx.x;
    if (i < NE) atomicAdd(&g_deg[dst[i]], 1);
    if (i < NN * DD / 4) {
        float4 v = __ldg((const float4*)feat + i);
        uint2 b;
        b.x = bf2pack(v.x, v.y);
        b.y = bf2pack(v.z, v.w);
        ((uint2*)g_fb)[i] = b;
    }
    if (i < DD * DD) {
        const float B1 = 0.6931471805599453f;  // log 2
        const float B2 = 0.4054651081081644f;  // log 1.5
        int n = i >> 7, k = i & 127;
        float ikn = (k == n) ? 1.f : 0.f;
        g_w1b[0][n * DD + k] = bf1(B1 * w11[k * DD + n] + (1.f - B1) * ikn);
        g_w2b[0][n * DD + k] = bf1(0.5f * (B1 * w21[k * DD + n] + (1.f - B1) * ikn));
        g_w1b[1][n * DD + k] = bf1(B2 * w12[k * DD + n] + (1.f - B2) * ikn);
        g_w2b[1][n * DD + k] = bf1(0.5f * (B2 * w22[k * DD + n] + (1.f - B2) * ikn));
    }
}

// fused scan: block-local scan + warp-parallel aggregate lookback + norm/gcnt
__global__ void k_scan(const int* __restrict__ gids) {
    __shared__ int s[1024];
    __shared__ int blockoff;
    int b = blockIdx.x, t = threadIdx.x;
    int i = b * 1024 + t;
    int v = (i < NN) ? g_deg[i] : 0;
    s[t] = v;
    __syncthreads();
    #pragma unroll
    for (int off = 1; off < 1024; off <<= 1) {
        int x = (t >= off) ? s[t - off] : 0;
        __syncthreads();
        s[t] += x;
        __syncthreads();
    }
    if (t == 1023)
        atomicExch(&g_agg[b], 0x80000000u | (unsigned)s[1023]);
    if (t < 32) {
        int sum = 0;
        for (int base = 0; base < b; base += 32) {
            int idx = base + t;
            unsigned val = 0;
            if (idx < b) {
                do { val = *(volatile unsigned*)&g_agg[idx]; }
                while (!(val & 0x80000000u));
            }
            sum += (int)(val & 0x7FFFFFFFu);
        }
        #pragma unroll
        for (int o = 16; o > 0; o >>= 1)
            sum += __shfl_down_sync(0xFFFFFFFFu, sum, o);
        if (t == 0) blockoff = sum;
    }
    __syncthreads();
    if (i < NN) {
        g_off[i] = blockoff + s[t] - v;
        g_norm[i] = rsqrtf((float)(v + 1));   // +1 self loop
        atomicAdd(&g_gcnt[gids[i]], 1);
    }
    if (i == NN) g_off[NN] = NE;
}

// fused: CSR fill + fp8 scaled feature (norm ⊙ feature) for the L1 gather
__global__ void k_fill(const int* __restrict__ src, const int* __restrict__ dst) {
    int i = blockIdx.x * blockDim.x + threadIdx.x;
    if (i < NE) {
        int d = dst[i];
        int p = g_off[d] + atomicAdd(&g_fill[d], 1);
        g_csr[p] = src[i];
    }
    if (i < NN * DD / 4) {
        int node = i >> 5;                  // 32 quads per row
        float nrm = g_norm[node];
        uint2 b = ((const uint2*)g_fb)[i];
        uint16_t p0 = fp8pack(bflo(b.x) * nrm, bfhi(b.x) * nrm);
        uint16_t p1 = fp8pack(bflo(b.y) * nrm, bfhi(b.y) * nrm);
        ((uint32_t*)g_fs)[i] = (uint32_t)p0 | ((uint32_t)p1 << 16);
    }
}

// ---- SpMM (fp8 gather, half2 accumulate): hs = bf16(0.5*nrm*(x̃[n]+Σx̃[src]))
// 16-lane node groups (uint2 = 8 fp8/lane), 8-edge unroll.
__global__ void k_spmm(const uint8_t* __restrict__ fin, uint16_t* __restrict__ fout) {
    int gt = blockIdx.x * blockDim.x + threadIdx.x;
    int node = gt >> 4, lane = gt & 15;
    if (node >= NN) return;
    const uint2* F = (const uint2*)fin;   // row = 128B = 16 x uint2
    uint2 a = __ldg(F + (size_t)node * 16 + lane);   // self loop (pre-scaled)
    uint32_t h[4];
    fp8x4_to_h2x2(a.x, h[0], h[1]);
    fp8x4_to_h2x2(a.y, h[2], h[3]);

    int beg = g_off[node], end = g_off[node + 1];
    int e = beg;
    for (; e + 8 <= end; e += 8) {
        uint2 v[8];
        #pragma unroll
        for (int j = 0; j < 8; j++) {
            int s = __ldg(g_csr + e + j);
            v[j] = __ldg(F + (size_t)s * 16 + lane);
        }
        #pragma unroll
        for (int j = 0; j < 8; j++) {
            uint32_t c0, c1, c2, c3;
            fp8x4_to_h2x2(v[j].x, c0, c1);
            fp8x4_to_h2x2(v[j].y, c2, c3);
            h[0] = hadd2(h[0], c0);
            h[1] = hadd2(h[1], c1);
            h[2] = hadd2(h[2], c2);
            h[3] = hadd2(h[3], c3);
        }
    }
    for (; e < end; e++) {
        int s = __ldg(g_csr + e);
        uint2 v0 = __ldg(F + (size_t)s * 16 + lane);
        uint32_t c0, c1, c2, c3;
        fp8x4_to_h2x2(v0.x, c0, c1);
        fp8x4_to_h2x2(v0.y, c2, c3);
        h[0] = hadd2(h[0], c0);
        h[1] = hadd2(h[1], c1);
        h[2] = hadd2(h[2], c2);
        h[3] = hadd2(h[3], c3);
    }
    float sc = 0.5f * g_norm[node];
    float2 f0 = h2f(h[0]), f1 = h2f(h[1]), f2 = h2f(h[2]), f3 = h2f(h[3]);
    uint4 o;
    o.x = bf2pack(f0.x * sc, f0.y * sc);
    o.y = bf2pack(f1.x * sc, f1.y * sc);
    o.z = bf2pack(f2.x * sc, f2.y * sc);
    o.w = bf2pack(f3.x * sc, f3.y * sc);
    ((uint4*)fout)[(size_t)node * 16 + lane] = o;
}

// ---- bf16 mma.sync GEMM: relu(hs@W1e + f0@W2e + b) ------------------------
// BM=128, BN=128, K=256 (hs|f0), BK=64 bf16 (128B rows), 4 chunks,
// 8 warps (warp tile 32x64), 2-stage cp.async pipeline, SW128 swizzle.
// MODE 0: write fp8 norm⊙x1 (feeds L2 gather). MODE 1: pool into g_pooled.
template <int MODE>
__global__ void __launch_bounds__(256, 2)
k_mma(const uint16_t* __restrict__ Ahs, const uint16_t* __restrict__ Af0,
      const uint16_t* __restrict__ Bw1, const uint16_t* __restrict__ Bw2,
      const float* __restrict__ bias, uint8_t* __restrict__ x8out,
      const int* __restrict__ gids) {
    extern __shared__ float smem[];   // 2 stages x (A 16KB + B 16KB)
    uint32_t sb = smem_u32(smem);
    int t = threadIdx.x, lane = t & 31, w = t >> 5;
    int wm = (w & 3) * 32, wn = (w >> 2) * 64;
    int R0 = blockIdx.x * 128;

    float acc[2][8][4];
    #pragma unroll
    for (int mt = 0; mt < 2; mt++)
        #pragma unroll
        for (int j = 0; j < 8; j++)
            #pragma unroll
            for (int q = 0; q < 4; q++) acc[mt][j][q] = 0.f;

    auto load_chunk = [&](int c) {
        int s = c & 1;
        uint32_t aB = sb + s * 32768;
        uint32_t bB = aB + 16384;
        const uint16_t* A = (c < 2) ? Ahs : Af0;
        const uint16_t* B = (c < 2) ? Bw1 : Bw2;
        int ko = (c & 1) * 64;
        #pragma unroll
        for (int i = 0; i < 4; i++) {
            int idx = i * 256 + t;
            int r = idx >> 3, f4 = idx & 7;
            int row = R0 + r; if (row >= NN) row = 0;
            uint32_t off = r * 128 + ((f4 * 16) ^ ((r & 7) << 4));
            cpa16(aB + off, A + (size_t)row * DD + ko + f4 * 8);
            cpa16(bB + off, B + (size_t)r * DD + ko + f4 * 8);
        }
        asm volatile("cp.async.commit_group;" ::: "memory");
    };

    load_chunk(0);
    load_chunk(1);

    int rA[2], rB[4];
    #pragma unroll
    for (int mt = 0; mt < 2; mt++)
        rA[mt] = wm + mt * 16 + (lane & 7) + ((lane >> 3) & 1) * 8;
    #pragma unroll
    for (int nt = 0; nt < 4; nt++)
        rB[nt] = wn + nt * 16 + (lane & 7) + ((lane >> 4) & 1) * 8;
    uint32_t aH = ((lane >> 4) & 1) * 16;
    uint32_t bH = ((lane >> 3) & 1) * 16;

    for (int c = 0; c < 4; c++) {
        int s = c & 1;
        if (c < 3) asm volatile("cp.async.wait_group 1;" ::: "memory");
        else       asm volatile("cp.async.wait_group 0;" ::: "memory");
        __syncthreads();

        uint32_t aB = sb + s * 32768;
        uint32_t bB = aB + 16384;
        #pragma unroll
        for (int kk = 0; kk < 4; kk++) {
            uint32_t a[2][4], b[4][4];
            #pragma unroll
            for (int mt = 0; mt < 2; mt++)
                ldsm4(a[mt], aB + rA[mt] * 128 +
                              (((uint32_t)(kk * 32) + aH) ^ ((rA[mt] & 7) << 4)));
            #pragma unroll
            for (int nt = 0; nt < 4; nt++)
                ldsm4(b[nt], bB + rB[nt] * 128 +
                              (((uint32_t)(kk * 32) + bH) ^ ((rB[nt] & 7) << 4)));
            #pragma unroll
            for (int mt = 0; mt < 2; mt++)
                #pragma unroll
                for (int nt = 0; nt < 4; nt++) {
                    mma16(acc[mt][2 * nt + 0], a[mt], b[nt][0], b[nt][1]);
                    mma16(acc[mt][2 * nt + 1], a[mt], b[nt][2], b[nt][3]);
                }
        }
        __syncthreads();
        if (c + 2 < 4) load_chunk(c + 2);
    }

    if (MODE == 0) {
        // epilogue: bias + relu + norm-prescale + fp8 pack
        #pragma unroll
        for (int mt = 0; mt < 2; mt++) {
            int row0 = R0 + wm + mt * 16 + (lane >> 2);
            float nr0 = (row0 < NN) ? g_norm[row0] : 0.f;
            float nr1 = (row0 + 8 < NN) ? g_norm[row0 + 8] : 0.f;
            #pragma unroll
            for (int j = 0; j < 8; j++) {
                int col = wn + j * 8 + (lane & 3) * 2;
                float2 bb = *(const float2*)(bias + col);
                float v0 = fmaxf(acc[mt][j][0] + bb.x, 0.f) * nr0;
                float v1 = fmaxf(acc[mt][j][1] + bb.y, 0.f) * nr0;
                float v2 = fmaxf(acc[mt][j][2] + bb.x, 0.f) * nr1;
                float v3 = fmaxf(acc[mt][j][3] + bb.y, 0.f) * nr1;
                if (row0 < NN)
                    *(uint16_t*)(x8out + (size_t)row0 * DD + col) = fp8pack(v0, v1);
                if (row0 + 8 < NN)
                    *(uint16_t*)(x8out + (size_t)(row0 + 8) * DD + col) = fp8pack(v2, v3);
            }
        }
    } else {
        // pooled epilogue: rows r0, r0+8, r0+16, r0+24 per thread
        int r0 = R0 + wm + (lane >> 2);
        int ra = r0, rb = r0 + 8, rc = r0 + 16, rd = r0 + 24;
        bool va = ra < NN, vb = rb < NN, vc = rc < NN, vd = rd < NN;
        if (va) {
            int ga = __ldg(gids + ra);
            int gb = vb ? __ldg(gids + rb) : ga;
            int gc = vc ? __ldg(gids + rc) : ga;
            int gd = vd ? __ldg(gids + rd) : ga;
            bool same = (ga == gb) && (gb == gc) && (gc == gd);
            #pragma unroll
            for (int j = 0; j < 8; j++) {
                int col = wn + j * 8 + (lane & 3) * 2;
                float2 bb = *(const float2*)(bias + col);
                #pragma unroll
                for (int q = 0; q < 2; q++) {
                    float bq = q ? bb.y : bb.x;
                    float u0 = va ? fmaxf(acc[0][j][q + 0] + bq, 0.f) : 0.f;
                    float u1 = vb ? fmaxf(acc[0][j][q + 2] + bq, 0.f) : 0.f;
                    float u2 = vc ? fmaxf(acc[1][j][q + 0] + bq, 0.f) : 0.f;
                    float u3 = vd ? fmaxf(acc[1][j][q + 2] + bq, 0.f) : 0.f;
                    if (same) {
                        atomicAdd(&g_pooled[ga * DD + col + q], u0 + u1 + u2 + u3);
                    } else {
                        atomicAdd(&g_pooled[ga * DD + col + q], u0);
                        if (vb) atomicAdd(&g_pooled[gb * DD + col + q], u1);
                        if (vc) atomicAdd(&g_pooled[gc * DD + col + q], u2);
                        if (vd) atomicAdd(&g_pooled[gd * DD + col + q], u3);
                    }
                }
            }
        }
    }
}

// ---------------- final MLP ----------------
__global__ void k_mlp(const float* __restrict__ d1w, const float* __restrict__ d1b,
                      const float* __restrict__ d2w, const float* __restrict__ d2b,
                      float* __restrict__ out) {
    int b = threadIdx.x;
    if (b >= NG) return;
    float inv = 1.f / fmaxf((float)g_gcnt[b], 1.f);
    float h[PHH];
    #pragma unroll
    for (int p = 0; p < PHH; p++) h[p] = __ldg(d1b + p);
    for (int c = 0; c < DD; c++) {
        float a = g_pooled[b * DD + c] * inv;
        #pragma unroll
        for (int p = 0; p < PHH; p++)
            h[p] = fmaf(a, __ldg(d1w + c * PHH + p), h[p]);
    }
    float z = __ldg(d2b);
    #pragma unroll
    for (int p = 0; p < PHH; p++)
        z = fmaf(fmaxf(h[p], 0.f), __ldg(d2w + p), z);
    out[b] = 1.f / (1.f + expf(-z));
}

// ---------------- launch ----------------
extern "C" void kernel_launch(void* const* d_in, const int* in_sizes, int n_in,
                              void* d_out, int out_size) {
    const float* feature = (const float*)d_in[0];
    const int*   src     = (const int*)d_in[1];
    const int*   dst     = (const int*)d_in[2];
    const int*   gids    = (const int*)d_in[3];
    const float* w1_1    = (const float*)d_in[4];
    const float* w2_1    = (const float*)d_in[5];
    const float* b_1     = (const float*)d_in[6];
    const float* w1_2    = (const float*)d_in[7];
    const float* w2_2    = (const float*)d_in[8];
    const float* b_2     = (const float*)d_in[9];
    const float* d1w     = (const float*)d_in[10];
    const float* d1b     = (const float*)d_in[11];
    const float* d2w     = (const float*)d_in[12];
    const float* d2b     = (const float*)d_in[13];
    float* out = (float*)d_out;

    uint16_t *fb_p = nullptr, *hb_p = nullptr, *w1b_p = nullptr, *w2b_p = nullptr;
    uint8_t *fs_p = nullptr, *xs_p = nullptr;
    cudaGetSymbolAddress((void**)&fb_p,  g_fb);
    cudaGetSymbolAddress((void**)&fs_p,  g_fs);
    cudaGetSymbolAddress((void**)&xs_p,  g_xs);
    cudaGetSymbolAddress((void**)&hb_p,  g_hb);
    cudaGetSymbolAddress((void**)&w1b_p, g_w1b);
    cudaGetSymbolAddress((void**)&w2b_p, g_w2b);

    const int SMEM_MMA = 65536;   // 2 stages x (A 16KB + B 16KB)
    cudaFuncSetAttribute(k_mma<0>, cudaFuncAttributeMaxDynamicSharedMemorySize, SMEM_MMA);
    cudaFuncSetAttribute(k_mma<1>, cudaFuncAttributeMaxDynamicSharedMemorySize, SMEM_MMA);

    k_zero<<<(NN + 255) / 256, 256>>>();
    k_pre<<<(NN * DD / 4 + 255) / 256, 256>>>(feature, dst, w1_1, w2_1, w1_2, w2_2);
    k_scan<<<NSB, 1024>>>(gids);
    k_fill<<<(NN * DD / 4 + 255) / 256, 256>>>(src, dst);

    // layer 1: spmm gathers fp8 norm⊙feature -> hs (bf16);
    //          gemm (hb, fb) -> fp8 norm⊙x1
    k_spmm<<<(NN * 16 + 255) / 256, 256>>>(fs_p, hb_p);
    k_mma<0><<<NTILES, 256, SMEM_MMA>>>(hb_p, fb_p, w1b_p, w2b_p, b_1, xs_p, gids);
    // layer 2: spmm gathers fp8 norm⊙x1 -> hs (bf16);
    //          gemm (hb, fb) pools directly into g_pooled
    k_spmm<<<(NN * 16 + 255) / 256, 256>>>(xs_p, hb_p);
    k_mma<1><<<NTILES, 256, SMEM_MMA>>>(hb_p, fb_p,
                                        w1b_p + DD * DD, w2b_p + DD * DD, b_2,
                                        nullptr, gids);
    // decoder
    k_mlp<<<1, 64>>>(d1w, d1b, d2w, d2b, out);
}